// round 3
// baseline (speedup 1.0000x reference)
#include <cuda_runtime.h>

#define NBATCH 2048
#define NT     48
#define NC     35
#define NE     19
#define NH     128
#define NG     512      // 4*NH
#define NC2    70       // 2*NC
#define RROWS  16
#define NTHR   256
#define NBLK   (NBATCH / RROWS)   // 128

// shared-memory strides (padded for conflict-free lane->row access)
#define STH 133   // h / c rows (128)
#define STG 517   // gate rows (512)
#define STC 37    // channel vectors (35)
#define STA 71    // cat / cc2 rows (70)
#define STE 667   // temp rows (665)

#define NPAIR (NE * NC)        // 665
#define NGRP  ((NPAIR + 3) / 4) // 167

// per-block, per-timestep loss partials: [block][t][5] = {msum, s1, s2, sq, s4}
__device__ float g_blk[NBLK * NT * 5];

static __device__ __forceinline__ float sigmoidf_(float v) {
    return 1.0f / (1.0f + __expf(-v));
}

__global__ __launch_bounds__(NTHR, 1)
void brits_main(const float* __restrict__ x, const float* __restrict__ mask,
                const float* __restrict__ delta,
                const float* __restrict__ w_dh, const float* __restrict__ b_dh,
                const float* __restrict__ w_dx, const float* __restrict__ b_dx,
                const float* __restrict__ w_hr, const float* __restrict__ b_hr,
                const float* __restrict__ w_fr, const float* __restrict__ b_fr,
                const float* __restrict__ w_comb, const float* __restrict__ b_comb,
                const float* __restrict__ w_ih, const float* __restrict__ w_hh,
                const float* __restrict__ b_ih, const float* __restrict__ b_hh,
                float* __restrict__ out_imp, float* __restrict__ out_ens)
{
    extern __shared__ float sm[];
    float* sh_h   = sm;                       // RROWS*STH
    float* sh_c   = sh_h  + RROWS * STH;      // RROWS*STH
    float* sh_g   = sh_c  + RROWS * STH;      // RROWS*STG
    float* sh_xt  = sh_g  + RROWS * STG;      // RROWS*STC
    float* sh_mt  = sh_xt + RROWS * STC;
    float* sh_dt  = sh_mt + RROWS * STC;
    float* sh_xh  = sh_dt + RROWS * STC;
    float* sh_zh  = sh_xh + RROWS * STC;
    float* sh_xc  = sh_zh + RROWS * STC;
    float* sh_cat = sh_xc + RROWS * STC;      // RROWS*STA  (gamma_x || mt)
    float* sh_cc2 = sh_cat+ RROWS * STA;      // RROWS*STA  (c_c || mt)
    float* sh_tp  = sh_cc2+ RROWS * STA;      // RROWS*STE  (temp_h per n,c)
    float* sh_red = sh_tp + RROWS * STE;      // 8 warps * 5

    const int tid  = threadIdx.x;
    const int lane = tid & 31;
    const int wrp  = tid >> 5;
    const int rowBase = blockIdx.x * RROWS;

    for (int i = tid; i < RROWS * STH; i += NTHR) { sh_h[i] = 0.f; sh_c[i] = 0.f; }
    __syncthreads();

    for (int t = 0; t < NT; ++t) {
        float lm = 0.f, l1 = 0.f, l2 = 0.f, lq = 0.f, l4 = 0.f;

        // ---- A: load xt, mt, dt; fill mt half of cat; msum partial ----
        for (int i = tid; i < RROWS * NC; i += NTHR) {
            int r = i / NC, c = i - r * NC;
            size_t gi = (size_t)(rowBase + r) * NT * NC + (size_t)t * NC + c;
            float xv = x[gi], mv = mask[gi], dv = delta[gi];
            sh_xt[r * STC + c] = xv;
            sh_mt[r * STC + c] = mv;
            sh_dt[r * STC + c] = dv;
            sh_cat[r * STA + NC + c] = mv;
            lm += mv;
        }
        __syncthreads();

        // ---- B1: gamma_x (diag temporal decay) -> cat[:, 0:35] ----
        for (int i = tid; i < RROWS * NC; i += NTHR) {
            int r = i / NC, c = i - r * NC;
            float dxd = __ldg(w_dx + c * NC + c);
            float gx = __expf(-fmaxf(sh_dt[r * STC + c] * dxd + __ldg(b_dx + c), 0.f));
            sh_cat[r * STA + c] = gx;
        }
        // ---- B2: gamma_h and decay h (4-row tile) ----
        for (int task = tid; task < NH * 4; task += NTHR) {
            int rg = task & 3, hh = task >> 2;
            int r0 = rg * 4;
            float a0 = 0.f, a1 = 0.f, a2 = 0.f, a3 = 0.f;
            const float* wr = w_dh + hh * NC;
            #pragma unroll 7
            for (int k = 0; k < NC; ++k) {
                float w = __ldg(wr + k);
                a0 += sh_dt[(r0 + 0) * STC + k] * w;
                a1 += sh_dt[(r0 + 1) * STC + k] * w;
                a2 += sh_dt[(r0 + 2) * STC + k] * w;
                a3 += sh_dt[(r0 + 3) * STC + k] * w;
            }
            float bb = __ldg(b_dh + hh);
            sh_h[(r0 + 0) * STH + hh] *= __expf(-fmaxf(a0 + bb, 0.f));
            sh_h[(r0 + 1) * STH + hh] *= __expf(-fmaxf(a1 + bb, 0.f));
            sh_h[(r0 + 2) * STH + hh] *= __expf(-fmaxf(a2 + bb, 0.f));
            sh_h[(r0 + 3) * STH + hh] *= __expf(-fmaxf(a3 + bb, 0.f));
        }
        __syncthreads();

        // ---- C: x_h = h @ w_hr^T + b_hr ; l1 ; x_c ----
        for (int task = tid; task < NC * 4; task += NTHR) {
            int rg = task & 3, c = task >> 2;
            int r0 = rg * 4;
            float a0 = 0.f, a1 = 0.f, a2 = 0.f, a3 = 0.f;
            const float* wr = w_hr + c * NH;
            #pragma unroll 8
            for (int k = 0; k < NH; ++k) {
                float w = __ldg(wr + k);
                a0 += sh_h[(r0 + 0) * STH + k] * w;
                a1 += sh_h[(r0 + 1) * STH + k] * w;
                a2 += sh_h[(r0 + 2) * STH + k] * w;
                a3 += sh_h[(r0 + 3) * STH + k] * w;
            }
            float bb = __ldg(b_hr + c);
            float av[4] = {a0, a1, a2, a3};
            #pragma unroll
            for (int rr = 0; rr < 4; ++rr) {
                int r = r0 + rr;
                float xh = av[rr] + bb;
                sh_xh[r * STC + c] = xh;
                float xt = sh_xt[r * STC + c], mt = sh_mt[r * STC + c];
                l1 += fabsf(xt - xh) * mt;
                sh_xc[r * STC + c] = mt * xt + (1.f - mt) * xh;
            }
        }
        __syncthreads();

        // ---- D: z_h = x_c @ (w_fr offdiag)^T + b_fr ; l2 ----
        for (int task = tid; task < NC * 4; task += NTHR) {
            int rg = task & 3, c = task >> 2;
            int r0 = rg * 4;
            float a0 = 0.f, a1 = 0.f, a2 = 0.f, a3 = 0.f;
            const float* wr = w_fr + c * NC;
            float wdiag = __ldg(wr + c);
            #pragma unroll 7
            for (int k = 0; k < NC; ++k) {
                float w = __ldg(wr + k);
                a0 += sh_xc[(r0 + 0) * STC + k] * w;
                a1 += sh_xc[(r0 + 1) * STC + k] * w;
                a2 += sh_xc[(r0 + 2) * STC + k] * w;
                a3 += sh_xc[(r0 + 3) * STC + k] * w;
            }
            float bb = __ldg(b_fr + c);
            float av[4] = {a0, a1, a2, a3};
            #pragma unroll
            for (int rr = 0; rr < 4; ++rr) {
                int r = r0 + rr;
                float z = av[rr] - wdiag * sh_xc[r * STC + c] + bb;
                sh_zh[r * STC + c] = z;
                l2 += fabsf(sh_xt[r * STC + c] - z) * sh_mt[r * STC + c];
            }
        }
        __syncthreads();

        // ---- E: alpha GEMM (4 rows x 4 (n,c) pairs), temp_h, quantile loss, ens out ----
        for (int task = tid; task < NGRP * 4; task += NTHR) {
            int rg = task & 3, grp = task >> 2;
            int r0 = rg * 4;
            int p0 = grp * 4;
            const float* wp[4];
            #pragma unroll
            for (int j = 0; j < 4; ++j) {
                int p = p0 + j; if (p > NPAIR - 1) p = NPAIR - 1;
                wp[j] = w_comb + (size_t)p * NC2;
            }
            float acc[16];
            #pragma unroll
            for (int q = 0; q < 16; ++q) acc[q] = 0.f;
            #pragma unroll 5
            for (int k = 0; k < NC2; ++k) {
                float a[4];
                #pragma unroll
                for (int rr = 0; rr < 4; ++rr) a[rr] = sh_cat[(r0 + rr) * STA + k];
                #pragma unroll
                for (int j = 0; j < 4; ++j) {
                    float w = __ldg(wp[j] + k);
                    #pragma unroll
                    for (int rr = 0; rr < 4; ++rr) acc[j * 4 + rr] += a[rr] * w;
                }
            }
            #pragma unroll
            for (int j = 0; j < 4; ++j) {
                int p = p0 + j;
                if (p < NPAIR) {
                    int n = p / NC, c = p - n * NC;
                    float bc = __ldg(b_comb + p);
                    float qn = (float)(n + 1) * 0.05f;
                    #pragma unroll
                    for (int rr = 0; rr < 4; ++rr) {
                        int r = r0 + rr;
                        float alpha = acc[j * 4 + rr] + bc;
                        float xh = sh_xh[r * STC + c];
                        float zh = sh_zh[r * STC + c];
                        float tp = xh + alpha * (zh - xh);
                        float xt = sh_xt[r * STC + c], mt = sh_mt[r * STC + c];
                        float wq = (xt <= tp) ? (1.f - qn) : qn;
                        lq += fabsf(tp - xt) * mt * wq;
                        sh_tp[r * STE + p] = tp;
                        out_ens[(((size_t)(rowBase + r) * NE + n) * NT + t) * NC + c]
                            = mt * xt + (1.f - mt) * tp;
                    }
                }
            }
        }
        __syncthreads();

        // ---- F: ensemble mean, l4, imputation out, build cc2 = [c_c || mt] ----
        for (int i = tid; i < RROWS * NC; i += NTHR) {
            int r = i / NC, c = i - r * NC;
            float s = 0.f;
            #pragma unroll
            for (int n = 0; n < NE; ++n) s += sh_tp[r * STE + n * NC + c];
            float mean = s * (1.0f / (float)NE);
            float xt = sh_xt[r * STC + c], mt = sh_mt[r * STC + c];
            l4 += fabsf(xt - mean) * mt;
            float cc = mt * xt + (1.f - mt) * mean;
            out_imp[((size_t)(rowBase + r) * NT + t) * NC + c] = cc;
            sh_cc2[r * STA + c] = cc;
            sh_cc2[r * STA + NC + c] = mt;
        }

        // ---- per-step loss reduce (deterministic, no atomics) ----
        float v0 = lm, v1 = l1, v2 = l2, v3 = lq, v4 = l4;
        #pragma unroll
        for (int o = 16; o > 0; o >>= 1) {
            v0 += __shfl_down_sync(0xffffffffu, v0, o);
            v1 += __shfl_down_sync(0xffffffffu, v1, o);
            v2 += __shfl_down_sync(0xffffffffu, v2, o);
            v3 += __shfl_down_sync(0xffffffffu, v3, o);
            v4 += __shfl_down_sync(0xffffffffu, v4, o);
        }
        if (lane == 0) {
            sh_red[wrp * 5 + 0] = v0; sh_red[wrp * 5 + 1] = v1;
            sh_red[wrp * 5 + 2] = v2; sh_red[wrp * 5 + 3] = v3;
            sh_red[wrp * 5 + 4] = v4;
        }
        __syncthreads();   // also the F -> G barrier (cc2 ready)
        if (tid == 0) {
            float s0 = 0.f, s1 = 0.f, s2 = 0.f, s3 = 0.f, s4 = 0.f;
            for (int w = 0; w < NTHR / 32; ++w) {
                s0 += sh_red[w * 5 + 0]; s1 += sh_red[w * 5 + 1];
                s2 += sh_red[w * 5 + 2]; s3 += sh_red[w * 5 + 3];
                s4 += sh_red[w * 5 + 4];
            }
            float* gp = g_blk + ((size_t)blockIdx.x * NT + t) * 5;
            gp[0] = s0; gp[1] = s1; gp[2] = s2; gp[3] = s3; gp[4] = s4;
        }

        // ---- G: gates = [c_c||mt] @ w_ih^T + h @ w_hh^T + biases (4x4 tile) ----
        for (int task = tid; task < NG; task += NTHR) {
            int rg = task & 3, g4 = task >> 2;   // g4: 0..127
            int g0 = g4 * 4;
            int r0 = rg * 4;
            float acc[16];
            #pragma unroll
            for (int q = 0; q < 16; ++q) acc[q] = 0.f;
            const float* wi = w_ih + (size_t)g0 * NC2;
            #pragma unroll 5
            for (int k = 0; k < NC2; ++k) {
                float a[4];
                #pragma unroll
                for (int rr = 0; rr < 4; ++rr) a[rr] = sh_cc2[(r0 + rr) * STA + k];
                #pragma unroll
                for (int j = 0; j < 4; ++j) {
                    float w = __ldg(wi + j * NC2 + k);
                    #pragma unroll
                    for (int rr = 0; rr < 4; ++rr) acc[j * 4 + rr] += a[rr] * w;
                }
            }
            const float* wh = w_hh + (size_t)g0 * NH;
            #pragma unroll 4
            for (int k = 0; k < NH; ++k) {
                float a[4];
                #pragma unroll
                for (int rr = 0; rr < 4; ++rr) a[rr] = sh_h[(r0 + rr) * STH + k];
                #pragma unroll
                for (int j = 0; j < 4; ++j) {
                    float w = __ldg(wh + j * NH + k);
                    #pragma unroll
                    for (int rr = 0; rr < 4; ++rr) acc[j * 4 + rr] += a[rr] * w;
                }
            }
            #pragma unroll
            for (int j = 0; j < 4; ++j) {
                float bias = __ldg(b_ih + g0 + j) + __ldg(b_hh + g0 + j);
                #pragma unroll
                for (int rr = 0; rr < 4; ++rr)
                    sh_g[(r0 + rr) * STG + g0 + j] = acc[j * 4 + rr] + bias;
            }
        }
        __syncthreads();

        // ---- H: LSTM cell update ----
        for (int i = tid; i < RROWS * NH; i += NTHR) {
            int r = i & (RROWS - 1), u = i >> 4;
            float gi_ = sh_g[r * STG + u];
            float gf_ = sh_g[r * STG + u + NH];
            float gg_ = sh_g[r * STG + u + 2 * NH];
            float go_ = sh_g[r * STG + u + 3 * NH];
            float si = sigmoidf_(gi_);
            float sf = sigmoidf_(gf_);
            float so = sigmoidf_(go_);
            float tg = tanhf(gg_);
            float cn = sf * sh_c[r * STH + u] + si * tg;
            sh_c[r * STH + u] = cn;
            sh_h[r * STH + u] = so * tanhf(cn);
        }
        __syncthreads();
    }
}

__global__ void brits_finalize(float* __restrict__ out)
{
    __shared__ double terms[NT];
    int t = threadIdx.x;
    if (t < NT) {
        double s0 = 0.0, s1 = 0.0, s2 = 0.0, s3 = 0.0, s4 = 0.0;
        for (int b = 0; b < NBLK; ++b) {
            const float* gp = g_blk + ((size_t)b * NT + t) * 5;
            s0 += (double)gp[0]; s1 += (double)gp[1]; s2 += (double)gp[2];
            s3 += (double)gp[3]; s4 += (double)gp[4];
        }
        double pm = s0 + 1e-5;
        terms[t] = (s1 + s2 + s4 + s3 / (double)NE) / pm;
    }
    __syncthreads();
    if (t == 0) {
        double s = 0.0;
        for (int i = 0; i < NT; ++i) s += terms[i];
        out[0] = (float)(s / (double)NT);
    }
}

extern "C" void kernel_launch(void* const* d_in, const int* in_sizes, int n_in,
                              void* d_out, int out_size)
{
    const float* x      = (const float*)d_in[0];
    const float* mask   = (const float*)d_in[1];
    const float* delta  = (const float*)d_in[2];
    const float* w_dh   = (const float*)d_in[3];
    const float* b_dh   = (const float*)d_in[4];
    const float* w_dx   = (const float*)d_in[5];
    const float* b_dx   = (const float*)d_in[6];
    const float* w_hr   = (const float*)d_in[7];
    const float* b_hr   = (const float*)d_in[8];
    const float* w_fr   = (const float*)d_in[9];
    const float* b_fr   = (const float*)d_in[10];
    const float* w_comb = (const float*)d_in[11];
    const float* b_comb = (const float*)d_in[12];
    const float* w_ih   = (const float*)d_in[13];
    const float* w_hh   = (const float*)d_in[14];
    const float* b_ih   = (const float*)d_in[15];
    const float* b_hh   = (const float*)d_in[16];

    float* out = (float*)d_out;
    float* out_imp = out + 1;
    float* out_ens = out_imp + (size_t)NBATCH * NT * NC;

    const int smem_bytes =
        (2 * RROWS * STH + RROWS * STG + 6 * RROWS * STC + 2 * RROWS * STA
         + RROWS * STE + 64) * (int)sizeof(float);

    cudaFuncSetAttribute(brits_main, cudaFuncAttributeMaxDynamicSharedMemorySize,
                         smem_bytes);

    brits_main<<<NBLK, NTHR, smem_bytes>>>(
        x, mask, delta, w_dh, b_dh, w_dx, b_dx, w_hr, b_hr, w_fr, b_fr,
        w_comb, b_comb, w_ih, w_hh, b_ih, b_hh, out_imp, out_ens);
    brits_finalize<<<1, 64>>>(out);
}

// round 4
// speedup vs baseline: 1.6862x; 1.6862x over previous
#include <cuda_runtime.h>

#define NBATCH 2048
#define NT     48
#define NC     35
#define NE     19
#define NH     128
#define NC2    70
#define RROWS  16
#define NTHR   256
#define NBLK   (NBATCH / RROWS)     // 128
#define NPAIR  (NE * NC)            // 665
#define NPGRP  168                  // ceil(672/4)
#define TPS    677                  // tp2 row stride (floats)
#define STS17  17                   // scalar-array stride

typedef unsigned long long u64;

// ---------------- device scratch (prepared weights) ----------------
__device__ float PW_FR[NC * NC];          // w_fr, diagonal zeroed
__device__ float PW_CB[672 * 72];         // w_comb padded [pair][k]
__device__ float PW_IH[NH * 4 * 72];      // [unit][gate][k] padded
__device__ float PW_HH[NH * 4 * NH];      // [unit][gate][k]
__device__ float PB_G[NH * 4];            // b_ih + b_hh per [unit][gate]
__device__ float PDX[NC];                 // diag(w_dx)
__device__ float g_blk[NBLK * NT * 5];    // loss partials

// ---------------- f32x2 helpers ----------------
static __device__ __forceinline__ u64 bcast2(float w) {
    u64 r; asm("mov.b64 %0, {%1, %1};" : "=l"(r) : "f"(w)); return r;
}
static __device__ __forceinline__ void fma2(u64& acc, u64 a, u64 b) {
    asm("fma.rn.f32x2 %0, %1, %2, %0;" : "+l"(acc) : "l"(a), "l"(b));
}
static __device__ __forceinline__ float2 unpack2(u64 v) {
    float2 f; asm("mov.b64 {%0, %1}, %2;" : "=f"(f.x), "=f"(f.y) : "l"(v)); return f;
}
static __device__ __forceinline__ float sigmoidf_(float v) {
    return 1.0f / (1.0f + __expf(-v));
}
static __device__ __forceinline__ float ftanh_(float v) {
    // tanh(x) = 1 - 2/(e^{2x}+1); saturates correctly at +/-inf of expf
    return 1.0f - __fdividef(2.0f, __expf(2.0f * v) + 1.0f);
}

// ---------------- prep: pad / reorder weights ----------------
__global__ void brits_prep(const float* __restrict__ w_fr,
                           const float* __restrict__ w_comb,
                           const float* __restrict__ w_ih,
                           const float* __restrict__ w_hh,
                           const float* __restrict__ b_ih,
                           const float* __restrict__ b_hh,
                           const float* __restrict__ w_dx)
{
    int i0 = blockIdx.x * blockDim.x + threadIdx.x;
    int n = gridDim.x * blockDim.x;
    for (int i = i0; i < 672 * 72; i += n) {
        int p = i / 72, k = i - p * 72;
        PW_CB[i] = (p < NPAIR && k < NC2) ? w_comb[p * NC2 + k] : 0.0f;
    }
    for (int i = i0; i < NH * 4 * 72; i += n) {
        int u = i / 288, rem = i - u * 288;
        int j = rem / 72, k = rem - j * 72;
        PW_IH[i] = (k < NC2) ? w_ih[(j * NH + u) * NC2 + k] : 0.0f;
    }
    for (int i = i0; i < NH * 4 * NH; i += n) {
        int u = i / 512, rem = i - u * 512;
        int j = rem / NH, k = rem - j * NH;
        PW_HH[i] = w_hh[(j * NH + u) * NH + k];
    }
    for (int i = i0; i < NC * NC; i += n) {
        int r = i / NC, c = i - r * NC;
        PW_FR[i] = (r == c) ? 0.0f : w_fr[i];
    }
    for (int i = i0; i < NH * 4; i += n) {
        int u = i >> 2, j = i & 3;
        PB_G[i] = b_ih[j * NH + u] + b_hh[j * NH + u];
    }
    for (int i = i0; i < NC; i += n) PDX[i] = w_dx[i * NC + i];
}

// ---------------- main persistent kernel ----------------
__global__ __launch_bounds__(NTHR, 1)
void brits_main(const float* __restrict__ x, const float* __restrict__ mask,
                const float* __restrict__ delta,
                const float* __restrict__ w_dh, const float* __restrict__ b_dh,
                const float* __restrict__ b_dx,
                const float* __restrict__ w_hr, const float* __restrict__ b_hr,
                const float* __restrict__ b_fr,
                const float* __restrict__ b_comb,
                float* __restrict__ out_imp, float* __restrict__ out_ens)
{
    extern __shared__ float sm[];
    // paired (stride-16, 8B/16B aligned pair access) arrays
    float* hA   = sm;                       // 128*16
    float* hB   = hA   + NH * 16;           // 128*16
    float* catT = hB   + NH * 16;           // 72*16
    float* cc2T = catT + 72 * 16;           // 72*16
    // scalar (stride-17) arrays
    float* cT   = cc2T + 72 * 16;           // 128*17
    float* dtT  = cT   + NH * STS17;        // 36*17
    float* xcT  = dtT  + 36 * STS17;        // 36*17
    float* xtT  = xcT  + 36 * STS17;        // 35*17
    float* mtT  = xtT  + NC * STS17;
    float* xhT  = mtT  + NC * STS17;
    float* zhT  = xhT  + NC * STS17;
    float* tp2  = zhT  + NC * STS17;        // 16*677
    float* sred = tp2  + RROWS * TPS;       // 40

    const int tid  = threadIdx.x;
    const int lane = tid & 31;
    const int wrp  = tid >> 5;
    const int rowBase = blockIdx.x * RROWS;

    // init
    for (int i = tid; i < NH * 16; i += NTHR) { hA[i] = 0.f; }
    for (int i = tid; i < NH * STS17; i += NTHR) cT[i] = 0.f;
    for (int i = tid; i < 2 * 16; i += NTHR) {      // zero pad rows 70,71
        catT[70 * 16 + i] = 0.f; cc2T[70 * 16 + i] = 0.f;
    }
    __syncthreads();

    float* hCur = hA;
    float* hNxt = hB;

    for (int t = 0; t < NT; ++t) {
        float lm = 0.f, l1 = 0.f, l2 = 0.f, lq = 0.f, l4 = 0.f;

        // ---- A: load xt/mt/dt transposed; mt half of cat ----
        for (int i = tid; i < RROWS * NC; i += NTHR) {
            int r = i / NC, c = i - r * NC;
            size_t gi = (size_t)(rowBase + r) * NT * NC + (size_t)t * NC + c;
            float xv = x[gi], mv = mask[gi], dv = delta[gi];
            xtT[c * STS17 + r] = xv;
            mtT[c * STS17 + r] = mv;
            dtT[c * STS17 + r] = dv;
            catT[(NC + c) * 16 + r] = mv;
            lm += mv;
        }
        __syncthreads();

        // ---- B1: gamma_x -> catT rows 0..34 ----
        for (int i = tid; i < NC * 16; i += NTHR) {
            int c = i >> 4, r = i & 15;
            float gx = __expf(-fmaxf(dtT[c * STS17 + r] * PDX[c] + __ldg(b_dx + c), 0.f));
            catT[c * 16 + r] = gx;
        }
        // ---- B2: gamma_h, decay hCur in place ----
        for (int task = tid; task < NH * 4; task += NTHR) {
            int rg = task & 3, hh = task >> 2;
            int r0 = rg * 4;
            float a0 = 0.f, a1 = 0.f, a2 = 0.f, a3 = 0.f;
            const float* wr = w_dh + hh * NC;
            #pragma unroll 7
            for (int k = 0; k < NC; ++k) {
                float w = __ldg(wr + k);
                a0 += dtT[k * STS17 + r0 + 0] * w;
                a1 += dtT[k * STS17 + r0 + 1] * w;
                a2 += dtT[k * STS17 + r0 + 2] * w;
                a3 += dtT[k * STS17 + r0 + 3] * w;
            }
            float bb = __ldg(b_dh + hh);
            hCur[hh * 16 + r0 + 0] *= __expf(-fmaxf(a0 + bb, 0.f));
            hCur[hh * 16 + r0 + 1] *= __expf(-fmaxf(a1 + bb, 0.f));
            hCur[hh * 16 + r0 + 2] *= __expf(-fmaxf(a2 + bb, 0.f));
            hCur[hh * 16 + r0 + 3] *= __expf(-fmaxf(a3 + bb, 0.f));
        }
        __syncthreads();

        // ---- C: x_h = h @ w_hr^T + b ; l1 ; x_c ----
        for (int task = tid; task < NC * 4; task += NTHR) {
            int rg = task & 3, c = task >> 2;
            int r0 = rg * 4;
            float a0 = 0.f, a1 = 0.f, a2 = 0.f, a3 = 0.f;
            const float* wr = w_hr + c * NH;
            #pragma unroll 8
            for (int k = 0; k < NH; ++k) {
                float w = __ldg(wr + k);
                a0 += hCur[k * 16 + r0 + 0] * w;
                a1 += hCur[k * 16 + r0 + 1] * w;
                a2 += hCur[k * 16 + r0 + 2] * w;
                a3 += hCur[k * 16 + r0 + 3] * w;
            }
            float bb = __ldg(b_hr + c);
            float av[4] = {a0, a1, a2, a3};
            #pragma unroll
            for (int rr = 0; rr < 4; ++rr) {
                int r = r0 + rr;
                float xh = av[rr] + bb;
                xhT[c * STS17 + r] = xh;
                float xt = xtT[c * STS17 + r], mt = mtT[c * STS17 + r];
                l1 += fabsf(xt - xh) * mt;
                xcT[c * STS17 + r] = mt * xt + (1.f - mt) * xh;
            }
        }
        __syncthreads();

        // ---- D: z_h = x_c @ PW_FR^T + b_fr ; l2 ----
        for (int task = tid; task < NC * 4; task += NTHR) {
            int rg = task & 3, c = task >> 2;
            int r0 = rg * 4;
            float a0 = 0.f, a1 = 0.f, a2 = 0.f, a3 = 0.f;
            const float* wr = PW_FR + c * NC;
            #pragma unroll 7
            for (int k = 0; k < NC; ++k) {
                float w = wr[k];
                a0 += xcT[k * STS17 + r0 + 0] * w;
                a1 += xcT[k * STS17 + r0 + 1] * w;
                a2 += xcT[k * STS17 + r0 + 2] * w;
                a3 += xcT[k * STS17 + r0 + 3] * w;
            }
            float bb = __ldg(b_fr + c);
            float av[4] = {a0, a1, a2, a3};
            #pragma unroll
            for (int rr = 0; rr < 4; ++rr) {
                int r = r0 + rr;
                float z = av[rr] + bb;
                zhT[c * STS17 + r] = z;
                l2 += fabsf(xtT[c * STS17 + r] - z) * mtT[c * STS17 + r];
            }
        }
        __syncthreads();

        // ---- E: alpha GEMM (f32x2: 8 rows x 4 pairs), temp_h, q-loss ----
        for (int task = tid; task < NPGRP * 2; task += NTHR) {
            int rg8 = task & 1, pg = task >> 1;
            int r0 = rg8 * 8;
            int p0 = pg * 4;
            u64 acc[4][4];
            #pragma unroll
            for (int j = 0; j < 4; ++j)
                #pragma unroll
                for (int pp = 0; pp < 4; ++pp) acc[j][pp] = 0ull;
            const float* w0 = PW_CB + p0 * 72;
            #pragma unroll 2
            for (int k0 = 0; k0 < 72; k0 += 4) {
                float4 w4[4];
                #pragma unroll
                for (int j = 0; j < 4; ++j)
                    w4[j] = *reinterpret_cast<const float4*>(w0 + j * 72 + k0);
                #pragma unroll
                for (int kk = 0; kk < 4; ++kk) {
                    int k = k0 + kk;
                    ulonglong2 aA = *reinterpret_cast<const ulonglong2*>(&catT[k * 16 + r0]);
                    ulonglong2 aB = *reinterpret_cast<const ulonglong2*>(&catT[k * 16 + r0 + 4]);
                    u64 ap0 = aA.x, ap1 = aA.y, ap2 = aB.x, ap3 = aB.y;
                    #pragma unroll
                    for (int j = 0; j < 4; ++j) {
                        float ws = (kk == 0) ? w4[j].x : (kk == 1) ? w4[j].y
                                 : (kk == 2) ? w4[j].z : w4[j].w;
                        u64 w2 = bcast2(ws);
                        fma2(acc[j][0], ap0, w2);
                        fma2(acc[j][1], ap1, w2);
                        fma2(acc[j][2], ap2, w2);
                        fma2(acc[j][3], ap3, w2);
                    }
                }
            }
            #pragma unroll
            for (int j = 0; j < 4; ++j) {
                int p = p0 + j;
                if (p >= NPAIR) continue;
                int n = p / NC, c = p - n * NC;
                float bc = __ldg(b_comb + p);
                float qn = (float)(n + 1) * 0.05f;
                #pragma unroll
                for (int pp = 0; pp < 4; ++pp) {
                    float2 av = unpack2(acc[j][pp]);
                    #pragma unroll
                    for (int rr = 0; rr < 2; ++rr) {
                        int r = r0 + pp * 2 + rr;
                        float alpha = (rr ? av.y : av.x) + bc;
                        float xh = xhT[c * STS17 + r];
                        float zh = zhT[c * STS17 + r];
                        float tp = xh + alpha * (zh - xh);
                        float xt = xtT[c * STS17 + r], mt = mtT[c * STS17 + r];
                        float wq = (xt <= tp) ? (1.f - qn) : qn;
                        lq += fabsf(tp - xt) * mt * wq;
                        tp2[r * TPS + p] = tp;
                    }
                }
            }
        }
        __syncthreads();

        // ---- F: ensemble mean, l4, build cc2T ----
        for (int i = tid; i < NC * 16; i += NTHR) {
            int c = i >> 4, r = i & 15;
            float s = 0.f;
            #pragma unroll
            for (int n = 0; n < NE; ++n) s += tp2[r * TPS + n * NC + c];
            float mean = s * (1.0f / (float)NE);
            float xt = xtT[c * STS17 + r], mt = mtT[c * STS17 + r];
            l4 += fabsf(xt - mean) * mt;
            float cc = mt * xt + (1.f - mt) * mean;
            cc2T[c * 16 + r] = cc;
            cc2T[(NC + c) * 16 + r] = mt;
        }

        // ---- loss reduce (deterministic) ----
        float v0 = lm, v1 = l1, v2 = l2, v3 = lq, v4 = l4;
        #pragma unroll
        for (int o = 16; o > 0; o >>= 1) {
            v0 += __shfl_down_sync(0xffffffffu, v0, o);
            v1 += __shfl_down_sync(0xffffffffu, v1, o);
            v2 += __shfl_down_sync(0xffffffffu, v2, o);
            v3 += __shfl_down_sync(0xffffffffu, v3, o);
            v4 += __shfl_down_sync(0xffffffffu, v4, o);
        }
        if (lane == 0) {
            sred[wrp * 5 + 0] = v0; sred[wrp * 5 + 1] = v1;
            sred[wrp * 5 + 2] = v2; sred[wrp * 5 + 3] = v3;
            sred[wrp * 5 + 4] = v4;
        }
        __syncthreads();   // F|G barrier (cc2T + sred ready)
        if (tid == 0) {
            float s0 = 0.f, s1 = 0.f, s2 = 0.f, s3 = 0.f, s4 = 0.f;
            for (int w = 0; w < NTHR / 32; ++w) {
                s0 += sred[w * 5 + 0]; s1 += sred[w * 5 + 1];
                s2 += sred[w * 5 + 2]; s3 += sred[w * 5 + 3];
                s4 += sred[w * 5 + 4];
            }
            float* gp = g_blk + ((size_t)blockIdx.x * NT + t) * 5;
            gp[0] = s0; gp[1] = s1; gp[2] = s2; gp[3] = s3; gp[4] = s4;
        }

        // ---- coalesced ensemble + imputation writes ----
        for (int r = 0; r < RROWS; ++r) {
            size_t gr = (size_t)(rowBase + r);
            for (int i = tid; i < NPAIR; i += NTHR) {
                int n = i / NC, c = i - n * NC;
                float tp = tp2[r * TPS + i];
                float xt = xtT[c * STS17 + r], mt = mtT[c * STS17 + r];
                out_ens[((gr * NE + n) * NT + t) * NC + c] = mt * xt + (1.f - mt) * tp;
            }
        }
        for (int i = tid; i < RROWS * NC; i += NTHR) {
            int r = i / NC, c = i - r * NC;
            out_imp[((size_t)(rowBase + r) * NT + t) * NC + c] = cc2T[c * 16 + r];
        }

        // ---- G: fused LSTM gates + cell update (f32x2) ----
        for (int task = tid; task < NH * 2; task += NTHR) {
            int rg8 = task & 1, u = task >> 1;
            int r0 = rg8 * 8;
            u64 acc[4][4];
            #pragma unroll
            for (int j = 0; j < 4; ++j)
                #pragma unroll
                for (int pp = 0; pp < 4; ++pp) acc[j][pp] = 0ull;

            const float* wi = PW_IH + u * 288;     // [4][72]
            #pragma unroll 2
            for (int k0 = 0; k0 < 72; k0 += 4) {
                float4 w4[4];
                #pragma unroll
                for (int j = 0; j < 4; ++j)
                    w4[j] = *reinterpret_cast<const float4*>(wi + j * 72 + k0);
                #pragma unroll
                for (int kk = 0; kk < 4; ++kk) {
                    int k = k0 + kk;
                    ulonglong2 aA = *reinterpret_cast<const ulonglong2*>(&cc2T[k * 16 + r0]);
                    ulonglong2 aB = *reinterpret_cast<const ulonglong2*>(&cc2T[k * 16 + r0 + 4]);
                    u64 ap0 = aA.x, ap1 = aA.y, ap2 = aB.x, ap3 = aB.y;
                    #pragma unroll
                    for (int j = 0; j < 4; ++j) {
                        float ws = (kk == 0) ? w4[j].x : (kk == 1) ? w4[j].y
                                 : (kk == 2) ? w4[j].z : w4[j].w;
                        u64 w2 = bcast2(ws);
                        fma2(acc[j][0], ap0, w2);
                        fma2(acc[j][1], ap1, w2);
                        fma2(acc[j][2], ap2, w2);
                        fma2(acc[j][3], ap3, w2);
                    }
                }
            }
            const float* wh = PW_HH + u * 512;     // [4][128]
            #pragma unroll 2
            for (int k0 = 0; k0 < NH; k0 += 4) {
                float4 w4[4];
                #pragma unroll
                for (int j = 0; j < 4; ++j)
                    w4[j] = *reinterpret_cast<const float4*>(wh + j * NH + k0);
                #pragma unroll
                for (int kk = 0; kk < 4; ++kk) {
                    int k = k0 + kk;
                    ulonglong2 aA = *reinterpret_cast<const ulonglong2*>(&hCur[k * 16 + r0]);
                    ulonglong2 aB = *reinterpret_cast<const ulonglong2*>(&hCur[k * 16 + r0 + 4]);
                    u64 ap0 = aA.x, ap1 = aA.y, ap2 = aB.x, ap3 = aB.y;
                    #pragma unroll
                    for (int j = 0; j < 4; ++j) {
                        float ws = (kk == 0) ? w4[j].x : (kk == 1) ? w4[j].y
                                 : (kk == 2) ? w4[j].z : w4[j].w;
                        u64 w2 = bcast2(ws);
                        fma2(acc[j][0], ap0, w2);
                        fma2(acc[j][1], ap1, w2);
                        fma2(acc[j][2], ap2, w2);
                        fma2(acc[j][3], ap3, w2);
                    }
                }
            }
            float bi = PB_G[u * 4 + 0], bf = PB_G[u * 4 + 1];
            float bg = PB_G[u * 4 + 2], bo = PB_G[u * 4 + 3];
            #pragma unroll
            for (int pp = 0; pp < 4; ++pp) {
                float2 gi2 = unpack2(acc[0][pp]);
                float2 gf2 = unpack2(acc[1][pp]);
                float2 gg2 = unpack2(acc[2][pp]);
                float2 go2 = unpack2(acc[3][pp]);
                #pragma unroll
                for (int rr = 0; rr < 2; ++rr) {
                    int r = r0 + pp * 2 + rr;
                    float gi_ = (rr ? gi2.y : gi2.x) + bi;
                    float gf_ = (rr ? gf2.y : gf2.x) + bf;
                    float gg_ = (rr ? gg2.y : gg2.x) + bg;
                    float go_ = (rr ? go2.y : go2.x) + bo;
                    float cn = sigmoidf_(gf_) * cT[u * STS17 + r]
                             + sigmoidf_(gi_) * ftanh_(gg_);
                    cT[u * STS17 + r] = cn;
                    hNxt[u * 16 + r] = sigmoidf_(go_) * ftanh_(cn);
                }
            }
        }
        __syncthreads();

        float* tmp = hCur; hCur = hNxt; hNxt = tmp;
    }
}

__global__ void brits_finalize(float* __restrict__ out)
{
    __shared__ double terms[NT];
    int w = threadIdx.x >> 5, lane = threadIdx.x & 31;
    for (int t = w; t < NT; t += 8) {
        double s0 = 0.0, s1 = 0.0, s2 = 0.0, s3 = 0.0, s4 = 0.0;
        for (int b = lane; b < NBLK; b += 32) {
            const float* gp = g_blk + ((size_t)b * NT + t) * 5;
            s0 += (double)gp[0]; s1 += (double)gp[1]; s2 += (double)gp[2];
            s3 += (double)gp[3]; s4 += (double)gp[4];
        }
        #pragma unroll
        for (int o = 16; o > 0; o >>= 1) {
            s0 += __shfl_down_sync(0xffffffffu, s0, o);
            s1 += __shfl_down_sync(0xffffffffu, s1, o);
            s2 += __shfl_down_sync(0xffffffffu, s2, o);
            s3 += __shfl_down_sync(0xffffffffu, s3, o);
            s4 += __shfl_down_sync(0xffffffffu, s4, o);
        }
        if (lane == 0) {
            double pm = s0 + 1e-5;
            terms[t] = (s1 + s2 + s4 + s3 / (double)NE) / pm;
        }
    }
    __syncthreads();
    if (threadIdx.x == 0) {
        double s = 0.0;
        for (int i = 0; i < NT; ++i) s += terms[i];
        out[0] = (float)(s / (double)NT);
    }
}

extern "C" void kernel_launch(void* const* d_in, const int* in_sizes, int n_in,
                              void* d_out, int out_size)
{
    const float* x      = (const float*)d_in[0];
    const float* mask   = (const float*)d_in[1];
    const float* delta  = (const float*)d_in[2];
    const float* w_dh   = (const float*)d_in[3];
    const float* b_dh   = (const float*)d_in[4];
    const float* w_dx   = (const float*)d_in[5];
    const float* b_dx   = (const float*)d_in[6];
    const float* w_hr   = (const float*)d_in[7];
    const float* b_hr   = (const float*)d_in[8];
    const float* w_fr   = (const float*)d_in[9];
    const float* b_fr   = (const float*)d_in[10];
    const float* w_comb = (const float*)d_in[11];
    const float* b_comb = (const float*)d_in[12];
    const float* w_ih   = (const float*)d_in[13];
    const float* w_hh   = (const float*)d_in[14];
    const float* b_ih   = (const float*)d_in[15];
    const float* b_hh   = (const float*)d_in[16];

    float* out = (float*)d_out;
    float* out_imp = out + 1;
    float* out_ens = out_imp + (size_t)NBATCH * NT * NC;

    const int smem_floats =
        2 * NH * 16 + 2 * 72 * 16 + NH * STS17 + 2 * 36 * STS17 +
        4 * NC * STS17 + RROWS * TPS + 48;
    const int smem_bytes = smem_floats * (int)sizeof(float);

    cudaFuncSetAttribute(brits_main, cudaFuncAttributeMaxDynamicSharedMemorySize,
                         smem_bytes);

    brits_prep<<<128, 256>>>(w_fr, w_comb, w_ih, w_hh, b_ih, b_hh, w_dx);
    brits_main<<<NBLK, NTHR, smem_bytes>>>(
        x, mask, delta, w_dh, b_dh, b_dx, w_hr, b_hr, b_fr, b_comb,
        out_imp, out_ens);
    brits_finalize<<<1, 256>>>(out);
}

// round 5
// speedup vs baseline: 2.2385x; 1.3275x over previous
#include <cuda_runtime.h>

#define NBATCH 2048
#define NT     48
#define NC     35
#define NE     19
#define NH     128
#define RROWS  16
#define NTHR   512
#define NBLK   128
#define NPAIR  665
#define EPAD   672
#define GKC    20
#define GCH    10
#define EKC    12
#define ECH    6
#define GCHFL  (NH * 4 * GKC)     // 10240 floats per G chunk
#define ECHFL  (EPAD * EKC)       // 8064 floats per E chunk

typedef unsigned long long u64;

// ---------------- prepared weights (device scratch) ----------------
__device__ float PW_G[GCH * GCHFL];   // [chunk][u][gate][20]
__device__ float PW_E[ECH * ECHFL];   // [chunk][pair][12]
__device__ float PW_FRd[NC * NC];     // diag-zeroed
__device__ float PB_Gd[NH * 4];       // b_ih+b_hh as [u][gate]
__device__ float PDXd[NC];            // diag(w_dx)
__device__ float g_blk[NBLK * NT * 5];

// ---------------- smem layout (floats) ----------------
#define O_AA   0
#define O_AB   3200
#define O_CT   6400          // 128*17
#define O_DTP  8576          // 35*16
#define O_XM   9136          // 35*17*2 (+pad)
#define O_XZ   10328
#define O_XCP  11520         // 35*16
#define O_CAT  12080         // 80*16
#define O_TPT  13360         // 672*17 (+pad)
#define O_WDH  24784         // 128*35
#define O_WHR  29264         // 35*128
#define O_WFR  33744         // 35*35 (+pad)
#define O_BIA  34976         // 1472
#define O_SRED 36448         // 80
#define O_WB   36528         // 2*10240
#define SMEM_FLOATS 57008

#define B_BDH 0
#define B_BHR 128
#define B_BFR 168
#define B_BDX 208
#define B_PDX 248
#define B_BCB 288
#define B_PBG 960

// ---------------- helpers ----------------
static __device__ __forceinline__ u64 bcast2(float w) {
    u64 r; asm("mov.b64 %0, {%1, %1};" : "=l"(r) : "f"(w)); return r;
}
static __device__ __forceinline__ void fma2(u64& acc, u64 a, u64 b) {
    asm("fma.rn.f32x2 %0, %1, %2, %0;" : "+l"(acc) : "l"(a), "l"(b));
}
static __device__ __forceinline__ float2 unpack2(u64 v) {
    float2 f; asm("mov.b64 {%0, %1}, %2;" : "=f"(f.x), "=f"(f.y) : "l"(v)); return f;
}
static __device__ __forceinline__ float sigmoidf_(float v) {
    return 1.0f / (1.0f + __expf(-v));
}
static __device__ __forceinline__ float ftanh_(float v) {
    return 1.0f - __fdividef(2.0f, __expf(2.0f * v) + 1.0f);
}
static __device__ __forceinline__ float getc4(float4 v, int kk) {
    return (kk == 0) ? v.x : (kk == 1) ? v.y : (kk == 2) ? v.z : v.w;
}

// ---------------- prep ----------------
__global__ void brits_prep(const float* __restrict__ w_fr,
                           const float* __restrict__ w_comb,
                           const float* __restrict__ w_ih,
                           const float* __restrict__ w_hh,
                           const float* __restrict__ b_ih,
                           const float* __restrict__ b_hh,
                           const float* __restrict__ w_dx)
{
    int i0 = blockIdx.x * blockDim.x + threadIdx.x;
    int n = gridDim.x * blockDim.x;
    for (int i = i0; i < GCH * GCHFL; i += n) {
        int c = i / GCHFL, rem = i - c * GCHFL;
        int u = rem / 80, rem2 = rem - u * 80;
        int j = rem2 / GKC, kk = rem2 - j * GKC;
        int k = c * GKC + kk;
        float v;
        if (k < 70)       v = w_ih[(j * NH + u) * 70 + k];
        else if (k < 72)  v = 0.0f;
        else              v = w_hh[(j * NH + u) * NH + (k - 72)];
        PW_G[i] = v;
    }
    for (int i = i0; i < ECH * ECHFL; i += n) {
        int c = i / ECHFL, rem = i - c * ECHFL;
        int p = rem / EKC, kk = rem - p * EKC;
        int k = c * EKC + kk;
        PW_E[i] = (p < NPAIR && k < 70) ? w_comb[p * 70 + k] : 0.0f;
    }
    for (int i = i0; i < NC * NC; i += n) {
        int r = i / NC, c = i - r * NC;
        PW_FRd[i] = (r == c) ? 0.0f : w_fr[i];
    }
    for (int i = i0; i < NH * 4; i += n) {
        int u = i >> 2, j = i & 3;
        PB_Gd[i] = b_ih[j * NH + u] + b_hh[j * NH + u];
    }
    for (int i = i0; i < NC; i += n) PDXd[i] = w_dx[i * NC + i];
}

// ---------------- main ----------------
__global__ __launch_bounds__(NTHR, 1)
void brits_main(const float* __restrict__ x, const float* __restrict__ mask,
                const float* __restrict__ delta,
                const float* __restrict__ w_dh, const float* __restrict__ b_dh,
                const float* __restrict__ b_dx,
                const float* __restrict__ w_hr, const float* __restrict__ b_hr,
                const float* __restrict__ b_fr,
                const float* __restrict__ b_comb,
                float* __restrict__ out_imp, float* __restrict__ out_ens)
{
    extern __shared__ float sm[];
    float* sAA  = sm + O_AA;
    float* sAB  = sm + O_AB;
    float* sCT  = sm + O_CT;
    float* sDTP = sm + O_DTP;
    float* sXM  = sm + O_XM;
    float* sXZ  = sm + O_XZ;
    float* sXCP = sm + O_XCP;
    float* sCAT = sm + O_CAT;
    float* sTPT = sm + O_TPT;
    float* sWDH = sm + O_WDH;
    float* sWHR = sm + O_WHR;
    float* sWFR = sm + O_WFR;
    float* sBIA = sm + O_BIA;
    float* sRED = sm + O_SRED;
    float* sWB  = sm + O_WB;

    const int tid  = threadIdx.x;
    const int lane = tid & 31;
    const int wrp  = tid >> 5;
    const int rowBase = blockIdx.x * RROWS;

    // one-time: resident small weights + biases, zero state
    for (int i = tid; i < NH * NC; i += NTHR) sWDH[i] = w_dh[i];
    for (int i = tid; i < NC * NH; i += NTHR) sWHR[i] = w_hr[i];
    for (int i = tid; i < NC * NC; i += NTHR) sWFR[i] = PW_FRd[i];
    for (int i = tid; i < NH; i += NTHR) sBIA[B_BDH + i] = b_dh[i];
    for (int i = tid; i < NC; i += NTHR) {
        sBIA[B_BHR + i] = b_hr[i];
        sBIA[B_BFR + i] = b_fr[i];
        sBIA[B_BDX + i] = b_dx[i];
        sBIA[B_PDX + i] = PDXd[i];
    }
    for (int i = tid; i < NPAIR; i += NTHR) sBIA[B_BCB + i] = b_comb[i];
    for (int i = tid; i < NH * 4; i += NTHR) sBIA[B_PBG + i] = PB_Gd[i];
    for (int i = tid; i < 3200; i += NTHR) { sAA[i] = 0.f; sAB[i] = 0.f; }
    for (int i = tid; i < NH * 17; i += NTHR) sCT[i] = 0.f;
    for (int i = tid; i < 160; i += NTHR) sCAT[70 * 16 + i] = 0.f;
    __syncthreads();

    float* aCur = sAA;
    float* aNxt = sAB;

    const int pgrp = tid >> 2;        // E: pair-group (6 pairs), valid < 112
    const int rgE  = tid & 3;
    const int r0e  = rgE * 4;
    const int uG   = tid >> 2;        // G: unit
    const int r0g  = (tid & 3) * 4;

    for (int t = 0; t < NT; ++t) {
        float lm = 0.f, l1 = 0.f, l2 = 0.f, lq = 0.f, l4 = 0.f;

        // ---- A: transposed loads ----
        for (int i = tid; i < RROWS * NC; i += NTHR) {
            int r = i / NC, c = i - r * NC;
            size_t gi = ((size_t)(rowBase + r) * NT + t) * NC + c;
            float xv = x[gi], mv = mask[gi], dv = delta[gi];
            sDTP[c * 16 + r] = dv;
            sXM[(c * 17 + r) * 2 + 0] = xv;
            sXM[(c * 17 + r) * 2 + 1] = mv;
            sCAT[(NC + c) * 16 + r] = mv;
            lm += mv;
        }
        __syncthreads();

        // ---- B1: gamma_x ----
        for (int i = tid; i < NC * 16; i += NTHR) {
            int c = i >> 4, r = i & 15;
            float gx = __expf(-fmaxf(sDTP[c * 16 + r] * sBIA[B_PDX + c]
                                     + sBIA[B_BDX + c], 0.f));
            sCAT[c * 16 + r] = gx;
        }
        // ---- B2: gamma_h decay (f32x2, 2 rows/task, 1024 tasks) ----
        for (int task = tid; task < NH * 8; task += NTHR) {
            int h = task >> 3, rg = task & 7, r0 = rg * 2;
            u64 a0 = 0ull, a1 = 0ull;
            const float* wr = sWDH + h * NC;
            #pragma unroll
            for (int k = 0; k < NC; ++k) {
                u64 d = *reinterpret_cast<const u64*>(&sDTP[k * 16 + r0]);
                if (k & 1) fma2(a1, d, bcast2(wr[k]));
                else       fma2(a0, d, bcast2(wr[k]));
            }
            float2 s0 = unpack2(a0), s1 = unpack2(a1);
            float bb = sBIA[B_BDH + h];
            aCur[(72 + h) * 16 + r0 + 0] *= __expf(-fmaxf(s0.x + s1.x + bb, 0.f));
            aCur[(72 + h) * 16 + r0 + 1] *= __expf(-fmaxf(s0.y + s1.y + bb, 0.f));
        }
        __syncthreads();

        // ---- C: x_h (f32x2, 2 rows/task, 280 tasks) ----
        if (tid < NC * 8) {
            int c = tid >> 3, rg = tid & 7, r0 = rg * 2;
            u64 a0 = 0ull, a1 = 0ull;
            const float* wr = sWHR + c * NH;
            #pragma unroll 4
            for (int k0 = 0; k0 < NH; k0 += 4) {
                float4 w = *reinterpret_cast<const float4*>(wr + k0);
                u64 h0 = *reinterpret_cast<const u64*>(&aCur[(72 + k0 + 0) * 16 + r0]);
                u64 h1 = *reinterpret_cast<const u64*>(&aCur[(72 + k0 + 1) * 16 + r0]);
                u64 h2 = *reinterpret_cast<const u64*>(&aCur[(72 + k0 + 2) * 16 + r0]);
                u64 h3 = *reinterpret_cast<const u64*>(&aCur[(72 + k0 + 3) * 16 + r0]);
                fma2(a0, h0, bcast2(w.x)); fma2(a1, h1, bcast2(w.y));
                fma2(a0, h2, bcast2(w.z)); fma2(a1, h3, bcast2(w.w));
            }
            float2 s0 = unpack2(a0), s1 = unpack2(a1);
            float bb = sBIA[B_BHR + c];
            float xh[2] = {s0.x + s1.x + bb, s0.y + s1.y + bb};
            #pragma unroll
            for (int rr = 0; rr < 2; ++rr) {
                int r = r0 + rr;
                sXZ[(c * 17 + r) * 2 + 0] = xh[rr];
                float xt = sXM[(c * 17 + r) * 2 + 0];
                float mt = sXM[(c * 17 + r) * 2 + 1];
                l1 += fabsf(xt - xh[rr]) * mt;
                sXCP[c * 16 + r] = mt * xt + (1.f - mt) * xh[rr];
            }
        }
        __syncthreads();

        // ---- D: z_h (f32x2, 2 rows/task) ----
        if (tid < NC * 8) {
            int c = tid >> 3, rg = tid & 7, r0 = rg * 2;
            u64 a0 = 0ull, a1 = 0ull;
            const float* wr = sWFR + c * NC;
            #pragma unroll
            for (int k = 0; k < NC; ++k) {
                u64 xp = *reinterpret_cast<const u64*>(&sXCP[k * 16 + r0]);
                if (k & 1) fma2(a1, xp, bcast2(wr[k]));
                else       fma2(a0, xp, bcast2(wr[k]));
            }
            float2 s0 = unpack2(a0), s1 = unpack2(a1);
            float bb = sBIA[B_BFR + c];
            #pragma unroll
            for (int rr = 0; rr < 2; ++rr) {
                int r = r0 + rr;
                float z = ((rr == 0) ? (s0.x + s1.x) : (s0.y + s1.y)) + bb;
                float xh = sXZ[(c * 17 + r) * 2 + 0];
                sXZ[(c * 17 + r) * 2 + 1] = z - xh;
                float xt = sXM[(c * 17 + r) * 2 + 0];
                float mt = sXM[(c * 17 + r) * 2 + 1];
                l2 += fabsf(xt - z) * mt;
            }
        }
        __syncthreads();

        // ---- E: alpha GEMM, smem-staged weights, double-buffered ----
        {
            u64 acc[6][2];
            #pragma unroll
            for (int j = 0; j < 6; ++j) { acc[j][0] = 0ull; acc[j][1] = 0ull; }
            float4 pre[4];
            {
                const float4* s = reinterpret_cast<const float4*>(PW_E);
                #pragma unroll
                for (int i = 0; i < 4; ++i) {
                    int idx = tid + i * NTHR;
                    if (idx < ECHFL / 4) pre[i] = s[idx];
                }
            }
            for (int ch = 0; ch < ECH; ++ch) {
                float* wb = sWB + (ch & 1) * GCHFL;
                float4* d4 = reinterpret_cast<float4*>(wb);
                #pragma unroll
                for (int i = 0; i < 4; ++i) {
                    int idx = tid + i * NTHR;
                    if (idx < ECHFL / 4) d4[idx] = pre[i];
                }
                if (ch + 1 < ECH) {
                    const float4* s = reinterpret_cast<const float4*>(PW_E + (ch + 1) * ECHFL);
                    #pragma unroll
                    for (int i = 0; i < 4; ++i) {
                        int idx = tid + i * NTHR;
                        if (idx < ECHFL / 4) pre[i] = s[idx];
                    }
                }
                __syncthreads();
                if (tid < 448) {
                    const float* wrow = wb + pgrp * 6 * EKC;
                    int kbase = ch * EKC;
                    #pragma unroll
                    for (int kk0 = 0; kk0 < EKC; kk0 += 4) {
                        float4 w[6];
                        #pragma unroll
                        for (int j = 0; j < 6; ++j)
                            w[j] = *reinterpret_cast<const float4*>(wrow + j * EKC + kk0);
                        #pragma unroll
                        for (int kk = 0; kk < 4; ++kk) {
                            ulonglong2 a2 = *reinterpret_cast<const ulonglong2*>(
                                &sCAT[(kbase + kk0 + kk) * 16 + r0e]);
                            #pragma unroll
                            for (int j = 0; j < 6; ++j) {
                                u64 b = bcast2(getc4(w[j], kk));
                                fma2(acc[j][0], a2.x, b);
                                fma2(acc[j][1], a2.y, b);
                            }
                        }
                    }
                }
            }
            // epilogue
            if (tid < 448) {
                #pragma unroll
                for (int j = 0; j < 6; ++j) {
                    int p = pgrp * 6 + j;
                    if (p < NPAIR) {
                        int n = p / NC, c = p - n * NC;
                        float bc = sBIA[B_BCB + p];
                        float qn = (float)(n + 1) * 0.05f;
                        #pragma unroll
                        for (int pp = 0; pp < 2; ++pp) {
                            float2 av = unpack2(acc[j][pp]);
                            #pragma unroll
                            for (int rr = 0; rr < 2; ++rr) {
                                int r = r0e + pp * 2 + rr;
                                float alpha = ((rr == 0) ? av.x : av.y) + bc;
                                float xh  = sXZ[(c * 17 + r) * 2 + 0];
                                float dzh = sXZ[(c * 17 + r) * 2 + 1];
                                float tp = xh + alpha * dzh;
                                float xt = sXM[(c * 17 + r) * 2 + 0];
                                float mt = sXM[(c * 17 + r) * 2 + 1];
                                float wq = (xt <= tp) ? (1.f - qn) : qn;
                                lq += fabsf(tp - xt) * mt * wq;
                                sTPT[p * 17 + r] = tp;
                            }
                        }
                    }
                }
            }
        }
        __syncthreads();

        // ---- F: ensemble mean, imp out, cc2 into aCur ----
        for (int i = tid; i < NC * 16; i += NTHR) {
            int c = i >> 4, r = i & 15;
            float s = 0.f;
            #pragma unroll
            for (int n = 0; n < NE; ++n) s += sTPT[(n * NC + c) * 17 + r];
            float mean = s * (1.0f / (float)NE);
            float xt = sXM[(c * 17 + r) * 2 + 0];
            float mt = sXM[(c * 17 + r) * 2 + 1];
            l4 += fabsf(xt - mean) * mt;
            float cc = mt * xt + (1.f - mt) * mean;
            out_imp[((size_t)(rowBase + r) * NT + t) * NC + c] = cc;
            aCur[c * 16 + r] = cc;
            aCur[(NC + c) * 16 + r] = mt;
        }
        // ---- ens writes (coalesced) ----
        for (int i = tid; i < RROWS * NPAIR; i += NTHR) {
            int r = i / NPAIR, pn = i - r * NPAIR;
            int n = pn / NC, c = pn - n * NC;
            float tp = sTPT[pn * 17 + r];
            float xt = sXM[(c * 17 + r) * 2 + 0];
            float mt = sXM[(c * 17 + r) * 2 + 1];
            out_ens[(((size_t)(rowBase + r) * NE + n) * NT + t) * NC + c]
                = mt * xt + (1.f - mt) * tp;
        }
        // ---- loss reduce ----
        {
            float v0 = lm, v1 = l1, v2 = l2, v3 = lq, v4 = l4;
            #pragma unroll
            for (int o = 16; o > 0; o >>= 1) {
                v0 += __shfl_down_sync(0xffffffffu, v0, o);
                v1 += __shfl_down_sync(0xffffffffu, v1, o);
                v2 += __shfl_down_sync(0xffffffffu, v2, o);
                v3 += __shfl_down_sync(0xffffffffu, v3, o);
                v4 += __shfl_down_sync(0xffffffffu, v4, o);
            }
            if (lane == 0) {
                sRED[wrp * 5 + 0] = v0; sRED[wrp * 5 + 1] = v1;
                sRED[wrp * 5 + 2] = v2; sRED[wrp * 5 + 3] = v3;
                sRED[wrp * 5 + 4] = v4;
            }
        }
        __syncthreads();
        if (tid == 0) {
            float s0 = 0.f, s1 = 0.f, s2 = 0.f, s3 = 0.f, s4 = 0.f;
            for (int w = 0; w < NTHR / 32; ++w) {
                s0 += sRED[w * 5 + 0]; s1 += sRED[w * 5 + 1];
                s2 += sRED[w * 5 + 2]; s3 += sRED[w * 5 + 3];
                s4 += sRED[w * 5 + 4];
            }
            float* gp = g_blk + ((size_t)blockIdx.x * NT + t) * 5;
            gp[0] = s0; gp[1] = s1; gp[2] = s2; gp[3] = s3; gp[4] = s4;
        }

        // ---- G: LSTM gates GEMM + fused cell update ----
        {
            u64 acc[4][2];
            #pragma unroll
            for (int j = 0; j < 4; ++j) { acc[j][0] = 0ull; acc[j][1] = 0ull; }
            float4 pre[5];
            {
                const float4* s = reinterpret_cast<const float4*>(PW_G);
                #pragma unroll
                for (int i = 0; i < 5; ++i) pre[i] = s[tid + i * NTHR];
            }
            for (int ch = 0; ch < GCH; ++ch) {
                float* wb = sWB + (ch & 1) * GCHFL;
                float4* d4 = reinterpret_cast<float4*>(wb);
                #pragma unroll
                for (int i = 0; i < 5; ++i) d4[tid + i * NTHR] = pre[i];
                if (ch + 1 < GCH) {
                    const float4* s = reinterpret_cast<const float4*>(PW_G + (ch + 1) * GCHFL);
                    #pragma unroll
                    for (int i = 0; i < 5; ++i) pre[i] = s[tid + i * NTHR];
                }
                __syncthreads();
                const float* wrow = wb + uG * 80;
                int kbase = ch * GKC;
                #pragma unroll
                for (int kk0 = 0; kk0 < GKC; kk0 += 4) {
                    float4 w0 = *reinterpret_cast<const float4*>(wrow + 0 * GKC + kk0);
                    float4 w1 = *reinterpret_cast<const float4*>(wrow + 1 * GKC + kk0);
                    float4 w2 = *reinterpret_cast<const float4*>(wrow + 2 * GKC + kk0);
                    float4 w3 = *reinterpret_cast<const float4*>(wrow + 3 * GKC + kk0);
                    #pragma unroll
                    for (int kk = 0; kk < 4; ++kk) {
                        ulonglong2 a2 = *reinterpret_cast<const ulonglong2*>(
                            &aCur[(kbase + kk0 + kk) * 16 + r0g]);
                        u64 b0 = bcast2(getc4(w0, kk));
                        fma2(acc[0][0], a2.x, b0); fma2(acc[0][1], a2.y, b0);
                        u64 b1 = bcast2(getc4(w1, kk));
                        fma2(acc[1][0], a2.x, b1); fma2(acc[1][1], a2.y, b1);
                        u64 b2 = bcast2(getc4(w2, kk));
                        fma2(acc[2][0], a2.x, b2); fma2(acc[2][1], a2.y, b2);
                        u64 b3 = bcast2(getc4(w3, kk));
                        fma2(acc[3][0], a2.x, b3); fma2(acc[3][1], a2.y, b3);
                    }
                }
            }
            // epilogue: cell update
            float bi = sBIA[B_PBG + uG * 4 + 0];
            float bf = sBIA[B_PBG + uG * 4 + 1];
            float bg = sBIA[B_PBG + uG * 4 + 2];
            float bo = sBIA[B_PBG + uG * 4 + 3];
            #pragma unroll
            for (int pp = 0; pp < 2; ++pp) {
                float2 gi2 = unpack2(acc[0][pp]);
                float2 gf2 = unpack2(acc[1][pp]);
                float2 gg2 = unpack2(acc[2][pp]);
                float2 go2 = unpack2(acc[3][pp]);
                #pragma unroll
                for (int rr = 0; rr < 2; ++rr) {
                    int r = r0g + pp * 2 + rr;
                    float gi_ = ((rr == 0) ? gi2.x : gi2.y) + bi;
                    float gf_ = ((rr == 0) ? gf2.x : gf2.y) + bf;
                    float gg_ = ((rr == 0) ? gg2.x : gg2.y) + bg;
                    float go_ = ((rr == 0) ? go2.x : go2.y) + bo;
                    float cn = sigmoidf_(gf_) * sCT[uG * 17 + r]
                             + sigmoidf_(gi_) * ftanh_(gg_);
                    sCT[uG * 17 + r] = cn;
                    aNxt[(72 + uG) * 16 + r] = sigmoidf_(go_) * ftanh_(cn);
                }
            }
        }
        __syncthreads();
        float* tmp = aCur; aCur = aNxt; aNxt = tmp;
    }
}

__global__ void brits_finalize(float* __restrict__ out)
{
    __shared__ double terms[NT];
    int w = threadIdx.x >> 5, lane = threadIdx.x & 31;
    for (int t = w; t < NT; t += 16) {
        double s0 = 0.0, s1 = 0.0, s2 = 0.0, s3 = 0.0, s4 = 0.0;
        for (int b = lane; b < NBLK; b += 32) {
            const float* gp = g_blk + ((size_t)b * NT + t) * 5;
            s0 += (double)gp[0]; s1 += (double)gp[1]; s2 += (double)gp[2];
            s3 += (double)gp[3]; s4 += (double)gp[4];
        }
        #pragma unroll
        for (int o = 16; o > 0; o >>= 1) {
            s0 += __shfl_down_sync(0xffffffffu, s0, o);
            s1 += __shfl_down_sync(0xffffffffu, s1, o);
            s2 += __shfl_down_sync(0xffffffffu, s2, o);
            s3 += __shfl_down_sync(0xffffffffu, s3, o);
            s4 += __shfl_down_sync(0xffffffffu, s4, o);
        }
        if (lane == 0) {
            double pm = s0 + 1e-5;
            terms[t] = (s1 + s2 + s4 + s3 / (double)NE) / pm;
        }
    }
    __syncthreads();
    if (threadIdx.x == 0) {
        double s = 0.0;
        for (int i = 0; i < NT; ++i) s += terms[i];
        out[0] = (float)(s / (double)NT);
    }
}

extern "C" void kernel_launch(void* const* d_in, const int* in_sizes, int n_in,
                              void* d_out, int out_size)
{
    const float* x      = (const float*)d_in[0];
    const float* mask   = (const float*)d_in[1];
    const float* delta  = (const float*)d_in[2];
    const float* w_dh   = (const float*)d_in[3];
    const float* b_dh   = (const float*)d_in[4];
    const float* w_dx   = (const float*)d_in[5];
    const float* b_dx   = (const float*)d_in[6];
    const float* w_hr   = (const float*)d_in[7];
    const float* b_hr   = (const float*)d_in[8];
    const float* w_fr   = (const float*)d_in[9];
    const float* b_fr   = (const float*)d_in[10];
    const float* w_comb = (const float*)d_in[11];
    const float* b_comb = (const float*)d_in[12];
    const float* w_ih   = (const float*)d_in[13];
    const float* w_hh   = (const float*)d_in[14];
    const float* b_ih   = (const float*)d_in[15];
    const float* b_hh   = (const float*)d_in[16];

    float* out = (float*)d_out;
    float* out_imp = out + 1;
    float* out_ens = out_imp + (size_t)NBATCH * NT * NC;

    const int smem_bytes = SMEM_FLOATS * (int)sizeof(float);
    cudaFuncSetAttribute(brits_main, cudaFuncAttributeMaxDynamicSharedMemorySize,
                         smem_bytes);

    brits_prep<<<256, 256>>>(w_fr, w_comb, w_ih, w_hh, b_ih, b_hh, w_dx);
    brits_main<<<NBLK, NTHR, smem_bytes>>>(
        x, mask, delta, w_dh, b_dh, b_dx, w_hr, b_hr, b_fr, b_comb,
        out_imp, out_ens);
    brits_finalize<<<1, 512>>>(out);
}